// round 1
// baseline (speedup 1.0000x reference)
#include <cuda_runtime.h>
#include <cuda_bf16.h>
#include <math.h>

#define N_NODES 10000
#define N_EDGES 160000
#define N_GRAPH 64
#define HID     128
#define H2      256
#define N_LAYER 14

// ---------------- device scratch (no allocations allowed) ----------------
__device__ float g_h[N_NODES * HID];
__device__ float g_r[N_NODES * HID];
__device__ float g_rnorm[N_NODES];
__device__ float g_Q[N_NODES * HID];
__device__ float g_P[N_NODES * HID];
__device__ float g_out[N_NODES * HID];
__device__ float g_z1[N_NODES * H2];
__device__ float g_a[N_NODES * H2];
__device__ int   g_deg[N_NODES];
__device__ int   g_rowptr[N_NODES + 1];
__device__ int   g_cursor[N_NODES];
__device__ int   g_col[N_EDGES];
__device__ float g_gsum[N_GRAPH * HID];
__device__ float g_cnt[N_GRAPH];

// ---------------- helpers ----------------
__device__ __forceinline__ unsigned long long pack2(float lo, float hi) {
    unsigned long long r;
    asm("mov.b64 %0, {%1,%2};" : "=l"(r) : "f"(lo), "f"(hi));
    return r;
}
__device__ __forceinline__ void unpack2(unsigned long long v, float& lo, float& hi) {
    asm("mov.b64 {%0,%1}, %2;" : "=f"(lo), "=f"(hi) : "l"(v));
}
#define FMA_F32X2(d, a, b, c) \
    asm("fma.rn.f32x2 %0, %1, %2, %3;" : "=l"(d) : "l"(a), "l"(b), "l"(c))

// block-wide sum, result broadcast to all threads. blockDim.x multiple of 32, <=256.
__device__ __forceinline__ float blockSum(float v, float* s) {
    #pragma unroll
    for (int o = 16; o; o >>= 1) v += __shfl_down_sync(0xffffffffu, v, o);
    __syncthreads();
    if ((threadIdx.x & 31) == 0) s[threadIdx.x >> 5] = v;
    __syncthreads();
    int nw = blockDim.x >> 5;
    float t = 0.f;
    for (int i = 0; i < nw; i++) t += s[i];
    return t;
}

// ---------------- CSR construction ----------------
__global__ void zero_csr_kernel() {
    int i = blockIdx.x * blockDim.x + threadIdx.x;
    if (i < N_NODES) g_deg[i] = 0;
}
__global__ void csr_count_kernel(const int* __restrict__ ei) {
    int e = blockIdx.x * blockDim.x + threadIdx.x;
    if (e < N_EDGES) atomicAdd(&g_deg[ei[N_EDGES + e]], 1);
}
__global__ void scan_kernel() {
    __shared__ int s[1024];
    const int CH = 10;  // 1024*10 >= 10000
    int t = threadIdx.x;
    int base = t * CH;
    int local[CH];
    int sum = 0;
    #pragma unroll
    for (int j = 0; j < CH; j++) {
        int idx = base + j;
        int v = (idx < N_NODES) ? g_deg[idx] : 0;
        local[j] = sum;
        sum += v;
    }
    s[t] = sum;
    __syncthreads();
    for (int off = 1; off < 1024; off <<= 1) {
        int v = (t >= off) ? s[t - off] : 0;
        __syncthreads();
        s[t] += v;
        __syncthreads();
    }
    int offset = (t > 0) ? s[t - 1] : 0;
    #pragma unroll
    for (int j = 0; j < CH; j++) {
        int idx = base + j;
        if (idx < N_NODES) {
            g_rowptr[idx] = offset + local[j];
            g_cursor[idx] = offset + local[j];
        }
    }
    if (t == 1023) g_rowptr[N_NODES] = s[1023];
}
__global__ void csr_fill_kernel(const int* __restrict__ ei) {
    int e = blockIdx.x * blockDim.x + threadIdx.x;
    if (e < N_EDGES) {
        int d = ei[N_EDGES + e];
        int p = atomicAdd(&g_cursor[d], 1);
        g_col[p] = ei[e];
    }
}

// ---------------- generic fused GEMM: C = A@B + bias (+Cin) ----------------
// A: [M,K] row-major, B: [K,N] row-major. BM=64, BN=128, BK=16, 256 threads.
// Requires K%16==0, N%128==0. M guarded.
__global__ __launch_bounds__(256) void gemm_kernel(
    const float* __restrict__ A, const float* __restrict__ B,
    const float* __restrict__ bias, const float* __restrict__ Cin,
    float* __restrict__ Cout, int M, int N, int K)
{
    __shared__ float As[16][64];   // [k][m]
    __shared__ float Bs[16][128];  // [k][n]
    int tid = threadIdx.x;
    int bm = blockIdx.y * 64;
    int bn = blockIdx.x * 128;
    int tr = tid >> 5;        // 0..7
    int tc = tid & 31;        // 0..31
    int row0 = tr * 8, col0 = tc * 4;

    unsigned long long acc[8][2];
    #pragma unroll
    for (int i = 0; i < 8; i++) { acc[i][0] = 0ull; acc[i][1] = 0ull; }

    int a_row = tid >> 2;          // 0..63
    int a_col = (tid & 3) * 4;     // 0,4,8,12

    for (int k0 = 0; k0 < K; k0 += 16) {
        float4 av = make_float4(0.f, 0.f, 0.f, 0.f);
        int gr = bm + a_row;
        if (gr < M) av = *(const float4*)&A[(size_t)gr * K + k0 + a_col];
        As[a_col + 0][a_row] = av.x;
        As[a_col + 1][a_row] = av.y;
        As[a_col + 2][a_row] = av.z;
        As[a_col + 3][a_row] = av.w;
        #pragma unroll
        for (int i = 0; i < 2; i++) {
            int f = tid + i * 256;
            int br = f >> 5, bc = (f & 31) * 4;
            *(float4*)&Bs[br][bc] = *(const float4*)&B[(size_t)(k0 + br) * N + bn + bc];
        }
        __syncthreads();
        #pragma unroll
        for (int k = 0; k < 16; k++) {
            float a[8];
            *(float4*)&a[0] = *(const float4*)&As[k][row0];
            *(float4*)&a[4] = *(const float4*)&As[k][row0 + 4];
            unsigned long long b0 = *(const unsigned long long*)&Bs[k][col0];
            unsigned long long b1 = *(const unsigned long long*)&Bs[k][col0 + 2];
            #pragma unroll
            for (int i = 0; i < 8; i++) {
                unsigned long long aa = pack2(a[i], a[i]);
                FMA_F32X2(acc[i][0], aa, b0, acc[i][0]);
                FMA_F32X2(acc[i][1], aa, b1, acc[i][1]);
            }
        }
        __syncthreads();
    }

    int c = bn + col0;
    float bv[4];
    bv[0] = bias[c + 0]; bv[1] = bias[c + 1]; bv[2] = bias[c + 2]; bv[3] = bias[c + 3];
    #pragma unroll
    for (int i = 0; i < 8; i++) {
        int r = bm + row0 + i;
        if (r >= M) break;
        float v[4];
        unpack2(acc[i][0], v[0], v[1]);
        unpack2(acc[i][1], v[2], v[3]);
        #pragma unroll
        for (int j = 0; j < 4; j++) v[j] += bv[j];
        if (Cin) {
            #pragma unroll
            for (int j = 0; j < 4; j++) v[j] += Cin[(size_t)r * N + c + j];
        }
        *(float4*)&Cout[(size_t)r * N + c] = make_float4(v[0], v[1], v[2], v[3]);
    }
}

// ---------------- per-node pre kernel: LN + leaky + msg precompute ----------------
__global__ __launch_bounds__(128) void node_pre_kernel(
    const float* __restrict__ ln_g, const float* __restrict__ ln_b,
    const float* __restrict__ tptr, int li)
{
    __shared__ float s[8];
    int n = blockIdx.x, f = threadIdx.x;
    float x = g_h[n * HID + f];
    float mu = blockSum(x, s) * (1.f / HID);
    float d = x - mu;
    float var = blockSum(d * d, s) * (1.f / HID);
    float y = d * rsqrtf(var + 1e-5f) * ln_g[li * HID + f] + ln_b[li * HID + f];
    float r = (y > 0.f) ? y : 0.01f * y;           // leaky_relu(0.01)
    g_r[n * HID + f] = r;
    float nrm2 = blockSum(r * r, s);
    if (f == 0) g_rnorm[n] = sqrtf(nrm2);
    float t = tptr[li];
    float m = fmaxf(y, 0.f) + 1e-7f;               // relu(leaky(y)) == relu(y)
    float q = expf(m * t);
    g_Q[n * HID + f] = q;
    g_P[n * HID + f] = m * q;
}

// ---------------- aggregation: softmax-agg + MessageNorm + residual ----------------
__global__ __launch_bounds__(128) void aggregate_kernel(
    const float* __restrict__ scptr, int li)
{
    __shared__ float s[8];
    int n = blockIdx.x, f = threadIdx.x;
    int st = g_rowptr[n], en = g_rowptr[n + 1];
    float num = 0.f, den = 0.f;
    int e = st;
    for (; e + 1 < en; e += 2) {
        int s0 = __ldg(&g_col[e]);
        int s1 = __ldg(&g_col[e + 1]);
        float p0 = g_P[s0 * HID + f], q0 = g_Q[s0 * HID + f];
        float p1 = g_P[s1 * HID + f], q1 = g_Q[s1 * HID + f];
        num += p0 + p1;
        den += q0 + q1;
    }
    if (e < en) {
        int s0 = __ldg(&g_col[e]);
        num += g_P[s0 * HID + f];
        den += g_Q[s0 * HID + f];
    }
    float agg = num / (den + 1e-16f);
    float n2 = blockSum(agg * agg, s);
    float inv = 1.f / fmaxf(sqrtf(n2), 1e-12f);
    float out = g_r[n * HID + f] + agg * inv * g_rnorm[n] * scptr[li];
    g_out[n * HID + f] = out;
}

// ---------------- LN(256) + relu on z1 ----------------
__global__ __launch_bounds__(256) void ln_relu_kernel(
    const float* __restrict__ mg, const float* __restrict__ mb, int li)
{
    __shared__ float s[8];
    int n = blockIdx.x, f = threadIdx.x;
    float x = g_z1[n * H2 + f];
    float mu = blockSum(x, s) * (1.f / H2);
    float d = x - mu;
    float var = blockSum(d * d, s) * (1.f / H2);
    float y = d * rsqrtf(var + 1e-5f) * mg[li * H2 + f] + mb[li * H2 + f];
    g_a[n * H2 + f] = fmaxf(y, 0.f);
}

// ---------------- final LN + leaky + pooled accumulation ----------------
__global__ void zero_pool_kernel() {
    int i = blockIdx.x * blockDim.x + threadIdx.x;
    if (i < N_GRAPH * HID) g_gsum[i] = 0.f;
    if (i < N_GRAPH) g_cnt[i] = 0.f;
}
__global__ __launch_bounds__(128) void final_kernel(
    const float* __restrict__ fn_g, const float* __restrict__ fn_b,
    const int* __restrict__ batch)
{
    __shared__ float s[8];
    int n = blockIdx.x, f = threadIdx.x;
    float x = g_h[n * HID + f];
    float mu = blockSum(x, s) * (1.f / HID);
    float d = x - mu;
    float var = blockSum(d * d, s) * (1.f / HID);
    float y = d * rsqrtf(var + 1e-5f) * fn_g[f] + fn_b[f];
    float v = (y > 0.f) ? y : 0.01f * y;
    int g = batch[n];
    atomicAdd(&g_gsum[g * HID + f], v);
    if (f == 0) atomicAdd(&g_cnt[g], 1.0f);
}
__global__ void pool_div_kernel(float* __restrict__ out) {
    int i = blockIdx.x * blockDim.x + threadIdx.x;
    if (i < N_GRAPH * HID) {
        int g = i >> 7;
        out[i] = g_gsum[i] / fmaxf(g_cnt[g], 1.0f);
    }
}

// ---------------- host launch ----------------
extern "C" void kernel_launch(void* const* d_in, const int* in_sizes, int n_in,
                              void* d_out, int out_size)
{
    const float* x     = (const float*)d_in[0];
    const int*   ei    = (const int*)d_in[1];   // [2,E] int32 (src row 0, dst row 1)
    const int*   batch = (const int*)d_in[2];
    const float* enc_W = (const float*)d_in[3];
    const float* enc_b = (const float*)d_in[4];
    const float* ln_g  = (const float*)d_in[5];
    const float* ln_b  = (const float*)d_in[6];
    const float* t     = (const float*)d_in[7];
    const float* sc    = (const float*)d_in[8];
    const float* W1    = (const float*)d_in[9];
    const float* b1    = (const float*)d_in[10];
    const float* mg    = (const float*)d_in[11];
    const float* mb    = (const float*)d_in[12];
    const float* W2    = (const float*)d_in[13];
    const float* b2    = (const float*)d_in[14];
    const float* fn_g  = (const float*)d_in[15];
    const float* fn_b  = (const float*)d_in[16];
    float* out = (float*)d_out;

    float *p_h, *p_out, *p_z1, *p_a;
    cudaGetSymbolAddress((void**)&p_h,   g_h);
    cudaGetSymbolAddress((void**)&p_out, g_out);
    cudaGetSymbolAddress((void**)&p_z1,  g_z1);
    cudaGetSymbolAddress((void**)&p_a,   g_a);

    const int MB = (N_NODES + 63) / 64;   // 157 row-blocks

    // CSR (edge_index is an input, so rebuild each call — ~20us)
    zero_csr_kernel<<<(N_NODES + 255) / 256, 256>>>();
    csr_count_kernel<<<(N_EDGES + 255) / 256, 256>>>(ei);
    scan_kernel<<<1, 1024>>>();
    csr_fill_kernel<<<(N_EDGES + 255) / 256, 256>>>(ei);

    // encoder: h = x @ enc_W + enc_b
    gemm_kernel<<<dim3(1, MB), 256>>>(x, enc_W, enc_b, nullptr, p_h,
                                      N_NODES, HID, HID);

    for (int li = 0; li < N_LAYER; li++) {
        node_pre_kernel<<<N_NODES, 128>>>(ln_g, ln_b, t, li);
        aggregate_kernel<<<N_NODES, 128>>>(sc, li);
        // z1 = out @ W1 + b1
        gemm_kernel<<<dim3(2, MB), 256>>>(p_out, W1 + (size_t)li * HID * H2,
                                          b1 + (size_t)li * H2, nullptr, p_z1,
                                          N_NODES, H2, HID);
        ln_relu_kernel<<<N_NODES, 256>>>(mg, mb, li);
        // h += a @ W2 + b2
        gemm_kernel<<<dim3(1, MB), 256>>>(p_a, W2 + (size_t)li * H2 * HID,
                                          b2 + (size_t)li * HID, p_h, p_h,
                                          N_NODES, HID, H2);
    }

    zero_pool_kernel<<<(N_GRAPH * HID + 255) / 256, 256>>>();
    final_kernel<<<N_NODES, 128>>>(fn_g, fn_b, batch);
    pool_div_kernel<<<(N_GRAPH * HID + 255) / 256, 256>>>(out);
}

// round 2
// speedup vs baseline: 1.0009x; 1.0009x over previous
#include <cuda_runtime.h>
#include <cuda_bf16.h>
#include <math.h>

#define N_NODES 10000
#define N_EDGES 160000
#define N_GRAPH 64
#define HID     128
#define H2      256
#define N_LAYER 14

// ---------------- device scratch (no allocations allowed) ----------------
__device__ float g_h[N_NODES * HID];
__device__ float g_r[N_NODES * HID];
__device__ float g_rnorm[N_NODES];
__device__ float g_Q[N_NODES * HID];
__device__ float g_P[N_NODES * HID];
__device__ float g_out[N_NODES * HID];
__device__ float g_z1[N_NODES * H2];
__device__ float g_a[N_NODES * H2];
__device__ int   g_deg[N_NODES];
__device__ int   g_rowptr[N_NODES + 1];
__device__ int   g_cursor[N_NODES];
__device__ int   g_col[N_EDGES];
__device__ float g_gsum[N_GRAPH * HID];
__device__ float g_cnt[N_GRAPH];

// ---------------- helpers ----------------
__device__ __forceinline__ unsigned long long pack2(float lo, float hi) {
    unsigned long long r;
    asm("mov.b64 %0, {%1,%2};" : "=l"(r) : "f"(lo), "f"(hi));
    return r;
}
__device__ __forceinline__ void unpack2(unsigned long long v, float& lo, float& hi) {
    asm("mov.b64 {%0,%1}, %2;" : "=f"(lo), "=f"(hi) : "l"(v));
}
#define FMA_F32X2(d, a, b, c) \
    asm("fma.rn.f32x2 %0, %1, %2, %3;" : "=l"(d) : "l"(a), "l"(b), "l"(c))

// block-wide sum, result broadcast to all threads. blockDim.x multiple of 32, <=256.
__device__ __forceinline__ float blockSum(float v, float* s) {
    #pragma unroll
    for (int o = 16; o; o >>= 1) v += __shfl_down_sync(0xffffffffu, v, o);
    __syncthreads();
    if ((threadIdx.x & 31) == 0) s[threadIdx.x >> 5] = v;
    __syncthreads();
    int nw = blockDim.x >> 5;
    float t = 0.f;
    for (int i = 0; i < nw; i++) t += s[i];
    return t;
}

// ---------------- CSR construction ----------------
__global__ void zero_csr_kernel() {
    int i = blockIdx.x * blockDim.x + threadIdx.x;
    if (i < N_NODES) g_deg[i] = 0;
}
__global__ void csr_count_kernel(const int* __restrict__ ei) {
    int e = blockIdx.x * blockDim.x + threadIdx.x;
    if (e < N_EDGES) atomicAdd(&g_deg[ei[N_EDGES + e]], 1);
}
__global__ void scan_kernel() {
    __shared__ int s[1024];
    const int CH = 10;  // 1024*10 >= 10000
    int t = threadIdx.x;
    int base = t * CH;
    int local[CH];
    int sum = 0;
    #pragma unroll
    for (int j = 0; j < CH; j++) {
        int idx = base + j;
        int v = (idx < N_NODES) ? g_deg[idx] : 0;
        local[j] = sum;
        sum += v;
    }
    s[t] = sum;
    __syncthreads();
    for (int off = 1; off < 1024; off <<= 1) {
        int v = (t >= off) ? s[t - off] : 0;
        __syncthreads();
        s[t] += v;
        __syncthreads();
    }
    int offset = (t > 0) ? s[t - 1] : 0;
    #pragma unroll
    for (int j = 0; j < CH; j++) {
        int idx = base + j;
        if (idx < N_NODES) {
            g_rowptr[idx] = offset + local[j];
            g_cursor[idx] = offset + local[j];
        }
    }
    if (t == 1023) g_rowptr[N_NODES] = s[1023];
}
__global__ void csr_fill_kernel(const int* __restrict__ ei) {
    int e = blockIdx.x * blockDim.x + threadIdx.x;
    if (e < N_EDGES) {
        int d = ei[N_EDGES + e];
        int p = atomicAdd(&g_cursor[d], 1);
        g_col[p] = ei[e];
    }
}

// ---------------- generic fused GEMM: C = A@B + bias (+Cin) ----------------
// A: [M,K] row-major, B: [K,N] row-major. BM=64, BN=128, BK=16, 256 threads.
// Requires K%16==0, N%128==0. M guarded.
__global__ __launch_bounds__(256) void gemm_kernel(
    const float* __restrict__ A, const float* __restrict__ B,
    const float* __restrict__ bias, const float* __restrict__ Cin,
    float* __restrict__ Cout, int M, int N, int K)
{
    __shared__ float As[16][64];   // [k][m]
    __shared__ float Bs[16][128];  // [k][n]
    int tid = threadIdx.x;
    int bm = blockIdx.y * 64;
    int bn = blockIdx.x * 128;
    int tr = tid >> 5;        // 0..7
    int tc = tid & 31;        // 0..31
    int row0 = tr * 8, col0 = tc * 4;

    unsigned long long acc[8][2];
    #pragma unroll
    for (int i = 0; i < 8; i++) { acc[i][0] = 0ull; acc[i][1] = 0ull; }

    int a_row = tid >> 2;          // 0..63
    int a_col = (tid & 3) * 4;     // 0,4,8,12

    for (int k0 = 0; k0 < K; k0 += 16) {
        float4 av = make_float4(0.f, 0.f, 0.f, 0.f);
        int gr = bm + a_row;
        if (gr < M) av = *(const float4*)&A[(size_t)gr * K + k0 + a_col];
        As[a_col + 0][a_row] = av.x;
        As[a_col + 1][a_row] = av.y;
        As[a_col + 2][a_row] = av.z;
        As[a_col + 3][a_row] = av.w;
        #pragma unroll
        for (int i = 0; i < 2; i++) {
            int f = tid + i * 256;
            int br = f >> 5, bc = (f & 31) * 4;
            *(float4*)&Bs[br][bc] = *(const float4*)&B[(size_t)(k0 + br) * N + bn + bc];
        }
        __syncthreads();
        #pragma unroll
        for (int k = 0; k < 16; k++) {
            float a[8];
            *(float4*)&a[0] = *(const float4*)&As[k][row0];
            *(float4*)&a[4] = *(const float4*)&As[k][row0 + 4];
            unsigned long long b0 = *(const unsigned long long*)&Bs[k][col0];
            unsigned long long b1 = *(const unsigned long long*)&Bs[k][col0 + 2];
            #pragma unroll
            for (int i = 0; i < 8; i++) {
                unsigned long long aa = pack2(a[i], a[i]);
                FMA_F32X2(acc[i][0], aa, b0, acc[i][0]);
                FMA_F32X2(acc[i][1], aa, b1, acc[i][1]);
            }
        }
        __syncthreads();
    }

    int c = bn + col0;
    float bv[4];
    bv[0] = bias[c + 0]; bv[1] = bias[c + 1]; bv[2] = bias[c + 2]; bv[3] = bias[c + 3];
    #pragma unroll
    for (int i = 0; i < 8; i++) {
        int r = bm + row0 + i;
        if (r >= M) break;
        float v[4];
        unpack2(acc[i][0], v[0], v[1]);
        unpack2(acc[i][1], v[2], v[3]);
        #pragma unroll
        for (int j = 0; j < 4; j++) v[j] += bv[j];
        if (Cin) {
            #pragma unroll
            for (int j = 0; j < 4; j++) v[j] += Cin[(size_t)r * N + c + j];
        }
        *(float4*)&Cout[(size_t)r * N + c] = make_float4(v[0], v[1], v[2], v[3]);
    }
}

// ---------------- per-node pre kernel: LN + leaky + msg precompute ----------------
__global__ __launch_bounds__(128) void node_pre_kernel(
    const float* __restrict__ ln_g, const float* __restrict__ ln_b,
    const float* __restrict__ tptr, int li)
{
    __shared__ float s[8];
    int n = blockIdx.x, f = threadIdx.x;
    float x = g_h[n * HID + f];
    float mu = blockSum(x, s) * (1.f / HID);
    float d = x - mu;
    float var = blockSum(d * d, s) * (1.f / HID);
    float y = d * rsqrtf(var + 1e-5f) * ln_g[li * HID + f] + ln_b[li * HID + f];
    float r = (y > 0.f) ? y : 0.01f * y;           // leaky_relu(0.01)
    g_r[n * HID + f] = r;
    float nrm2 = blockSum(r * r, s);
    if (f == 0) g_rnorm[n] = sqrtf(nrm2);
    float t = tptr[li];
    float m = fmaxf(y, 0.f) + 1e-7f;               // relu(leaky(y)) == relu(y)
    float q = expf(m * t);
    g_Q[n * HID + f] = q;
    g_P[n * HID + f] = m * q;
}

// ---------------- aggregation: softmax-agg + MessageNorm + residual ----------------
__global__ __launch_bounds__(128) void aggregate_kernel(
    const float* __restrict__ scptr, int li)
{
    __shared__ float s[8];
    int n = blockIdx.x, f = threadIdx.x;
    int st = g_rowptr[n], en = g_rowptr[n + 1];
    float num = 0.f, den = 0.f;
    int e = st;
    for (; e + 1 < en; e += 2) {
        int s0 = __ldg(&g_col[e]);
        int s1 = __ldg(&g_col[e + 1]);
        float p0 = g_P[s0 * HID + f], q0 = g_Q[s0 * HID + f];
        float p1 = g_P[s1 * HID + f], q1 = g_Q[s1 * HID + f];
        num += p0 + p1;
        den += q0 + q1;
    }
    if (e < en) {
        int s0 = __ldg(&g_col[e]);
        num += g_P[s0 * HID + f];
        den += g_Q[s0 * HID + f];
    }
    float agg = num / (den + 1e-16f);
    float n2 = blockSum(agg * agg, s);
    float inv = 1.f / fmaxf(sqrtf(n2), 1e-12f);
    float out = g_r[n * HID + f] + agg * inv * g_rnorm[n] * scptr[li];
    g_out[n * HID + f] = out;
}

// ---------------- LN(256) + relu on z1 ----------------
__global__ __launch_bounds__(256) void ln_relu_kernel(
    const float* __restrict__ mg, const float* __restrict__ mb, int li)
{
    __shared__ float s[8];
    int n = blockIdx.x, f = threadIdx.x;
    float x = g_z1[n * H2 + f];
    float mu = blockSum(x, s) * (1.f / H2);
    float d = x - mu;
    float var = blockSum(d * d, s) * (1.f / H2);
    float y = d * rsqrtf(var + 1e-5f) * mg[li * H2 + f] + mb[li * H2 + f];
    g_a[n * H2 + f] = fmaxf(y, 0.f);
}

// ---------------- final LN + leaky + pooled accumulation ----------------
__global__ void zero_pool_kernel() {
    int i = blockIdx.x * blockDim.x + threadIdx.x;
    if (i < N_GRAPH * HID) g_gsum[i] = 0.f;
    if (i < N_GRAPH) g_cnt[i] = 0.f;
}
__global__ __launch_bounds__(128) void final_kernel(
    const float* __restrict__ fn_g, const float* __restrict__ fn_b,
    const int* __restrict__ batch)
{
    __shared__ float s[8];
    int n = blockIdx.x, f = threadIdx.x;
    float x = g_h[n * HID + f];
    float mu = blockSum(x, s) * (1.f / HID);
    float d = x - mu;
    float var = blockSum(d * d, s) * (1.f / HID);
    float y = d * rsqrtf(var + 1e-5f) * fn_g[f] + fn_b[f];
    float v = (y > 0.f) ? y : 0.01f * y;
    int g = batch[n];
    atomicAdd(&g_gsum[g * HID + f], v);
    if (f == 0) atomicAdd(&g_cnt[g], 1.0f);
}
__global__ void pool_div_kernel(float* __restrict__ out) {
    int i = blockIdx.x * blockDim.x + threadIdx.x;
    if (i < N_GRAPH * HID) {
        int g = i >> 7;
        out[i] = g_gsum[i] / fmaxf(g_cnt[g], 1.0f);
    }
}

// ---------------- host launch ----------------
extern "C" void kernel_launch(void* const* d_in, const int* in_sizes, int n_in,
                              void* d_out, int out_size)
{
    const float* x     = (const float*)d_in[0];
    const int*   ei    = (const int*)d_in[1];   // [2,E] int32 (src row 0, dst row 1)
    const int*   batch = (const int*)d_in[2];
    const float* enc_W = (const float*)d_in[3];
    const float* enc_b = (const float*)d_in[4];
    const float* ln_g  = (const float*)d_in[5];
    const float* ln_b  = (const float*)d_in[6];
    const float* t     = (const float*)d_in[7];
    const float* sc    = (const float*)d_in[8];
    const float* W1    = (const float*)d_in[9];
    const float* b1    = (const float*)d_in[10];
    const float* mg    = (const float*)d_in[11];
    const float* mb    = (const float*)d_in[12];
    const float* W2    = (const float*)d_in[13];
    const float* b2    = (const float*)d_in[14];
    const float* fn_g  = (const float*)d_in[15];
    const float* fn_b  = (const float*)d_in[16];
    float* out = (float*)d_out;

    float *p_h, *p_out, *p_z1, *p_a;
    cudaGetSymbolAddress((void**)&p_h,   g_h);
    cudaGetSymbolAddress((void**)&p_out, g_out);
    cudaGetSymbolAddress((void**)&p_z1,  g_z1);
    cudaGetSymbolAddress((void**)&p_a,   g_a);

    const int MB = (N_NODES + 63) / 64;   // 157 row-blocks

    // CSR (edge_index is an input, so rebuild each call — ~20us)
    zero_csr_kernel<<<(N_NODES + 255) / 256, 256>>>();
    csr_count_kernel<<<(N_EDGES + 255) / 256, 256>>>(ei);
    scan_kernel<<<1, 1024>>>();
    csr_fill_kernel<<<(N_EDGES + 255) / 256, 256>>>(ei);

    // encoder: h = x @ enc_W + enc_b
    gemm_kernel<<<dim3(1, MB), 256>>>(x, enc_W, enc_b, nullptr, p_h,
                                      N_NODES, HID, HID);

    for (int li = 0; li < N_LAYER; li++) {
        node_pre_kernel<<<N_NODES, 128>>>(ln_g, ln_b, t, li);
        aggregate_kernel<<<N_NODES, 128>>>(sc, li);
        // z1 = out @ W1 + b1
        gemm_kernel<<<dim3(2, MB), 256>>>(p_out, W1 + (size_t)li * HID * H2,
                                          b1 + (size_t)li * H2, nullptr, p_z1,
                                          N_NODES, H2, HID);
        ln_relu_kernel<<<N_NODES, 256>>>(mg, mb, li);
        // h += a @ W2 + b2
        gemm_kernel<<<dim3(1, MB), 256>>>(p_a, W2 + (size_t)li * H2 * HID,
                                          b2 + (size_t)li * HID, p_h, p_h,
                                          N_NODES, HID, H2);
    }

    zero_pool_kernel<<<(N_GRAPH * HID + 255) / 256, 256>>>();
    final_kernel<<<N_NODES, 128>>>(fn_g, fn_b, batch);
    pool_div_kernel<<<(N_GRAPH * HID + 255) / 256, 256>>>(out);
}